// round 4
// baseline (speedup 1.0000x reference)
#include <cuda_runtime.h>
#include <cuda_bf16.h>
#include <cstdint>

// Problem constants
#define BB   16
#define UU   1024
#define HH   8
#define CC   128          // head dim = U/H
#define SS   1024
#define SCALE 0.08838834764831843f   // 1/sqrt(128)

#define NMASK ((size_t)BB * SS * SS)

// ---------------------------------------------------------------------------
// Scratch (device globals; allocation inside kernel_launch is forbidden)
// ---------------------------------------------------------------------------
__device__ float g_qkv[(size_t)BB * 3 * UU * SS];   // (B, 3U, S)  201 MB
__device__ float g_ctx[(size_t)BB * UU * SS];       // (B, U, S)    67 MB
__device__ float g_coef[BB * SS];                   // scale / rowcount
__device__ unsigned char g_mask[NMASK];             // canonical 0/1 bytes, 16 MB
__device__ int g_mode;                              // 0=u8, 1=i32, 2=f32

// ---------------------------------------------------------------------------
// Kernel A: detect mask element width from byte pattern of raw buffer.
//   uint8 random 0/1 : nonzero bytes at all positions mod 4
//   int32 0/1 (LE)   : nonzero only at position 0 mod 4
//   float32 0.0/1.0  : nonzero only at positions 2,3 mod 4 (0x3F800000)
// Scans first 1 MB (raw buffer is >= 16 MB in every interpretation).
// ---------------------------------------------------------------------------
__global__ void detect_mask_kernel(const unsigned char* __restrict__ raw) {
    __shared__ int nz[4];
    if (threadIdx.x < 4) nz[threadIdx.x] = 0;
    __syncthreads();
    int c0 = 0, c1 = 0;
    for (int i = threadIdx.x * 4; i < (1 << 20); i += blockDim.x * 4) {
        uchar4 v = *(const uchar4*)(raw + i);
        c0 += (v.x != 0);
        c1 += (v.y != 0);
    }
    atomicAdd(&nz[0], c0);
    atomicAdd(&nz[1], c1);
    __syncthreads();
    if (threadIdx.x == 0) {
        int mode;
        if (nz[1] > 0)      mode = 0;   // byte-width data
        else if (nz[0] > 0) mode = 1;   // int32 0/1
        else                mode = 2;   // float32 0.0/1.0
        g_mode = mode;
    }
}

// ---------------------------------------------------------------------------
// Kernel B: normalize raw mask -> uint8 0/1
// ---------------------------------------------------------------------------
__global__ void normalize_mask_kernel(const void* __restrict__ raw,
                                      unsigned char* __restrict__ dst) {
    size_t i = (size_t)blockIdx.x * blockDim.x + threadIdx.x;
    if (i >= NMASK) return;
    int mode = g_mode;
    unsigned char v;
    if (mode == 0)      v = ((const unsigned char*)raw)[i] != 0;
    else if (mode == 1) v = ((const int*)raw)[i] != 0;
    else                v = ((const float*)raw)[i] != 0.0f;
    dst[i] = v;
}

// ---------------------------------------------------------------------------
// Kernel 0: coef[b,q] = SCALE / max(1, sum_k mask[b,q,k])
// ---------------------------------------------------------------------------
__global__ void coef_kernel(const unsigned char* __restrict__ mask,
                            float* __restrict__ coef) {
    int row = blockIdx.x;                // b*S + q
    int tid = threadIdx.x;               // 256 threads, 4 bytes each
    const uchar4 v = ((const uchar4*)(mask + (size_t)row * SS))[tid];
    int s = (int)v.x + (int)v.y + (int)v.z + (int)v.w;
#pragma unroll
    for (int o = 16; o; o >>= 1) s += __shfl_xor_sync(0xffffffffu, s, o);
    __shared__ int red[8];
    if ((tid & 31) == 0) red[tid >> 5] = s;
    __syncthreads();
    if (tid < 8) {
        int t = red[tid];
#pragma unroll
        for (int o = 4; o; o >>= 1) t += __shfl_xor_sync(0xffu, t, o);
        if (tid == 0) coef[row] = SCALE / (float)(t > 0 ? t : 1);
    }
}

// ---------------------------------------------------------------------------
// Kernel 1/3: row-major NN GEMM  C[b] = A @ B[b]
// A: MxK (shared across batch), B: KxN per batch, C: MxN per batch.
// 128x128 tile, BK=8, 256 threads, 8x8 microtile.
// ---------------------------------------------------------------------------
__global__ void __launch_bounds__(256, 2)
gemm_nn(const float* __restrict__ A, const float* __restrict__ B,
        float* __restrict__ C, int M, int N, int K,
        size_t bStride, size_t cStride) {
    __shared__ float As[8][128];
    __shared__ float Bs[8][128];

    const float* Bp = B + (size_t)blockIdx.z * bStride;
    float*       Cp = C + (size_t)blockIdx.z * cStride;
    const int m0 = blockIdx.y * 128;
    const int n0 = blockIdx.x * 128;
    const int tid = threadIdx.x;

    const int mA = tid >> 1;            // 0..127
    const int kA = (tid & 1) * 4;       // 0 or 4
    const int kB = tid >> 5;            // 0..7
    const int nB = (tid & 31) * 4;      // 0..124
    const int mC = (tid >> 4) * 8;
    const int nC = (tid & 15) * 8;

    float acc[8][8];
#pragma unroll
    for (int i = 0; i < 8; i++)
#pragma unroll
        for (int j = 0; j < 8; j++) acc[i][j] = 0.f;

    for (int k0 = 0; k0 < K; k0 += 8) {
        float4 av = *(const float4*)&A [(size_t)(m0 + mA) * K + k0 + kA];
        float4 bv = *(const float4*)&Bp[(size_t)(k0 + kB) * N + n0 + nB];
        __syncthreads();   // previous compute finished before overwrite
        As[kA + 0][mA] = av.x;
        As[kA + 1][mA] = av.y;
        As[kA + 2][mA] = av.z;
        As[kA + 3][mA] = av.w;
        *(float4*)&Bs[kB][nB] = bv;
        __syncthreads();
#pragma unroll
        for (int kk = 0; kk < 8; kk++) {
            float4 a0 = *(const float4*)&As[kk][mC];
            float4 a1 = *(const float4*)&As[kk][mC + 4];
            float4 b0 = *(const float4*)&Bs[kk][nC];
            float4 b1 = *(const float4*)&Bs[kk][nC + 4];
            float a[8] = {a0.x, a0.y, a0.z, a0.w, a1.x, a1.y, a1.z, a1.w};
            float b[8] = {b0.x, b0.y, b0.z, b0.w, b1.x, b1.y, b1.z, b1.w};
#pragma unroll
            for (int i = 0; i < 8; i++)
#pragma unroll
                for (int j = 0; j < 8; j++) acc[i][j] += a[i] * b[j];
        }
    }
#pragma unroll
    for (int i = 0; i < 8; i++) {
        float* crow = &Cp[(size_t)(m0 + mC + i) * N + n0 + nC];
        *(float4*)&crow[0] = make_float4(acc[i][0], acc[i][1], acc[i][2], acc[i][3]);
        *(float4*)&crow[4] = make_float4(acc[i][4], acc[i][5], acc[i][6], acc[i][7]);
    }
}

// ---------------------------------------------------------------------------
// Kernel 2: fused masked-relu attention (no softmax!)
// per (b,h): A[q,k] = sum_c Q[c,q]K[c,k];  A' = mask ? relu(A)*coef[q] : 0
//            ctx[c,q] = sum_k A'[q,k] V[c,k]
// Block: 64 queries of one (b,h). 256 threads.
// ---------------------------------------------------------------------------
#define AS_STRIDE 65
#define ATTN_SMEM_FLOATS (3 * CC * 64 + 64 * AS_STRIDE + 64)
#define ATTN_SMEM_BYTES  (ATTN_SMEM_FLOATS * 4 + 64 * 64)

__global__ void __launch_bounds__(256)
attn_kernel(const float* __restrict__ qkv, const unsigned char* __restrict__ mask,
            const float* __restrict__ coef, float* __restrict__ ctx) {
    extern __shared__ float sm[];
    float* Qs = sm;                       // [128][64]
    float* Ks = Qs + CC * 64;             // [128][64]
    float* Vs = Ks + CC * 64;             // [128][64]
    float* As = Vs + CC * 64;             // [64][AS_STRIDE] (k-major)
    float* coefs = As + 64 * AS_STRIDE;   // [64]
    unsigned char* msk = (unsigned char*)(coefs + 64);  // [64][64]

    const int q0 = blockIdx.x * 64;
    const int h  = blockIdx.y;
    const int b  = blockIdx.z;
    const int tid = threadIdx.x;

    const float* Qg = qkv + ((size_t)b * 3 * UU + (size_t)h * CC) * SS;
    const float* Kg = Qg + (size_t)UU * SS;
    const float* Vg = Qg + (size_t)2 * UU * SS;
    const unsigned char* mg = mask + ((size_t)b * SS + q0) * SS;

    // Q tile (resident) + coefs
#pragma unroll
    for (int t = 0; t < 8; t++) {
        int idx = tid + t * 256;
        int c = idx >> 4, kg = (idx & 15) << 2;
        *(float4*)&Qs[c * 64 + kg] = *(const float4*)&Qg[(size_t)c * SS + q0 + kg];
    }
    if (tid < 64) coefs[tid] = coef[b * SS + q0 + tid];

    const int qA = (tid & 15) * 4;        // phase-A query offset (== phase-B)
    const int kA = (tid >> 4) * 4;        // phase-A key offset
    const int cB = (tid >> 4) * 8;        // phase-B channel offset

    float acc[4][8];
#pragma unroll
    for (int i = 0; i < 4; i++)
#pragma unroll
        for (int u = 0; u < 8; u++) acc[i][u] = 0.f;

    for (int kt = 0; kt < SS / 64; kt++) {
        const int k0 = kt * 64;
        __syncthreads();                  // prior phase-B reads of Vs/As done
#pragma unroll
        for (int t = 0; t < 8; t++) {
            int idx = tid + t * 256;
            int c = idx >> 4, kg = (idx & 15) << 2;
            *(float4*)&Ks[c * 64 + kg] = *(const float4*)&Kg[(size_t)c * SS + k0 + kg];
            *(float4*)&Vs[c * 64 + kg] = *(const float4*)&Vg[(size_t)c * SS + k0 + kg];
        }
#pragma unroll
        for (int t = 0; t < 4; t++) {
            int idx = tid + t * 256;
            int q = idx >> 4, kg = (idx & 15) << 2;
            *(uchar4*)&msk[q * 64 + kg] = *(const uchar4*)&mg[(size_t)q * SS + k0 + kg];
        }
        __syncthreads();                  // tiles visible

        // Phase A: 4q x 4k scores over 128 channels
        float a4[4][4];
#pragma unroll
        for (int i = 0; i < 4; i++)
#pragma unroll
            for (int j = 0; j < 4; j++) a4[i][j] = 0.f;
#pragma unroll 8
        for (int c = 0; c < CC; c++) {
            float4 qv = *(const float4*)&Qs[c * 64 + qA];
            float4 kv = *(const float4*)&Ks[c * 64 + kA];
            float qr[4] = {qv.x, qv.y, qv.z, qv.w};
            float kr[4] = {kv.x, kv.y, kv.z, kv.w};
#pragma unroll
            for (int i = 0; i < 4; i++)
#pragma unroll
                for (int j = 0; j < 4; j++) a4[i][j] += qr[i] * kr[j];
        }
        // mask + relu + coef, stage to smem (k-major)
#pragma unroll
        for (int j = 0; j < 4; j++)
#pragma unroll
            for (int i = 0; i < 4; i++) {
                float v = 0.f;
                if (msk[(qA + i) * 64 + kA + j]) {
                    float r = a4[i][j];
                    v = (r > 0.f ? r : 0.f) * coefs[qA + i];
                }
                As[(kA + j) * AS_STRIDE + qA + i] = v;
            }
        __syncthreads();                  // A' visible

        // Phase B: ctx[q, c] += sum_k A'[q,k] * V[c,k]
#pragma unroll 8
        for (int kk = 0; kk < 64; kk++) {
            float a0 = As[kk * AS_STRIDE + qA + 0];
            float a1 = As[kk * AS_STRIDE + qA + 1];
            float a2 = As[kk * AS_STRIDE + qA + 2];
            float a3 = As[kk * AS_STRIDE + qA + 3];
#pragma unroll
            for (int u = 0; u < 8; u++) {
                float vv = Vs[(cB + u) * 64 + kk];
                acc[0][u] += a0 * vv;
                acc[1][u] += a1 * vv;
                acc[2][u] += a2 * vv;
                acc[3][u] += a3 * vv;
            }
        }
    }

    // epilogue: ctx[b, h*128 + c, q]
#pragma unroll
    for (int u = 0; u < 8; u++) {
        float* crow = &ctx[((size_t)b * UU + (size_t)h * CC + cB + u) * SS + q0 + qA];
        *(float4*)crow = make_float4(acc[0][u], acc[1][u], acc[2][u], acc[3][u]);
    }
}

// ---------------------------------------------------------------------------
// Launch
// ---------------------------------------------------------------------------
extern "C" void kernel_launch(void* const* d_in, const int* in_sizes, int n_in,
                              void* d_out, int out_size) {
    const float* x     = (const float*)d_in[0];
    const void*  maskr = d_in[1];
    const float* w_qkv = (const float*)d_in[2];
    const float* w_out = (const float*)d_in[3];
    float*       out   = (float*)d_out;

    void *p_qkv, *p_ctx, *p_coef, *p_mask;
    cudaGetSymbolAddress(&p_qkv,  g_qkv);
    cudaGetSymbolAddress(&p_ctx,  g_ctx);
    cudaGetSymbolAddress(&p_coef, g_coef);
    cudaGetSymbolAddress(&p_mask, g_mask);
    float* qkv  = (float*)p_qkv;
    float* ctx  = (float*)p_ctx;
    float* coef = (float*)p_coef;
    unsigned char* mask = (unsigned char*)p_mask;

    // A/B) detect mask dtype and normalize to uint8 0/1
    detect_mask_kernel<<<1, 256>>>((const unsigned char*)maskr);
    normalize_mask_kernel<<<(int)(NMASK / 256), 256>>>(maskr, mask);

    // 0) mask row coefficients
    coef_kernel<<<BB * SS, 256>>>(mask, coef);

    // 1) QKV projection: (3072x1024) @ x[b](1024x1024)
    gemm_nn<<<dim3(SS / 128, 3 * UU / 128, BB), 256>>>(
        w_qkv, x, qkv, 3 * UU, SS, UU,
        (size_t)UU * SS, (size_t)3 * UU * SS);

    // 2) fused attention
    cudaFuncSetAttribute(attn_kernel,
                         cudaFuncAttributeMaxDynamicSharedMemorySize,
                         ATTN_SMEM_BYTES);
    attn_kernel<<<dim3(SS / 64, HH, BB), 256, ATTN_SMEM_BYTES>>>(
        qkv, mask, coef, ctx);

    // 3) output projection: (1024x1024) @ ctx[b](1024x1024)
    gemm_nn<<<dim3(SS / 128, UU / 128, BB), 256>>>(
        w_out, ctx, out, UU, SS, UU,
        (size_t)UU * SS, (size_t)UU * SS);
}

// round 8
// speedup vs baseline: 1.3213x; 1.3213x over previous
#include <cuda_runtime.h>
#include <cuda_bf16.h>
#include <mma.h>
#include <cstdint>

using namespace nvcuda;

// Problem constants
#define BB   16
#define UU   1024
#define HH   8
#define CC   128          // head dim = U/H
#define SS   1024
#define SCALE 0.08838834764831843f   // 1/sqrt(128)

#define NMASK ((size_t)BB * SS * SS)

// ---------------------------------------------------------------------------
// Scratch (device globals; allocation inside kernel_launch is forbidden)
// ---------------------------------------------------------------------------
__device__ float g_qkv[(size_t)BB * 3 * UU * SS];   // (B, 3U, S) fp32, 201 MB
__device__ float g_ctx[(size_t)BB * UU * SS];       // (B, U, S)  fp32,  67 MB
__device__ float g_coef[BB * SS];                   // scale / rowcount
__device__ unsigned char g_mask[NMASK];             // canonical 0/1 bytes, 16 MB
__device__ int g_mode;                              // 0=u8, 1=i32, 2=f32
// planar split-bf16 operands (hi plane + lo plane, both K-major [row][1024])
__device__ __nv_bfloat16 g_wq_h[(size_t)3 * UU * UU];
__device__ __nv_bfloat16 g_wq_l[(size_t)3 * UU * UU];
__device__ __nv_bfloat16 g_wo_h[(size_t)UU * UU];
__device__ __nv_bfloat16 g_wo_l[(size_t)UU * UU];
__device__ __nv_bfloat16 g_xt_h[(size_t)BB * UU * SS];   // x^T  (b, s, u)
__device__ __nv_bfloat16 g_xt_l[(size_t)BB * UU * SS];
__device__ __nv_bfloat16 g_ct_h[(size_t)BB * UU * SS];   // ctx^T (b, s, u)
__device__ __nv_bfloat16 g_ct_l[(size_t)BB * UU * SS];

// ---------------------------------------------------------------------------
// Mask dtype detect + normalize (proven in R4)
// ---------------------------------------------------------------------------
__global__ void detect_mask_kernel(const unsigned char* __restrict__ raw) {
    __shared__ int nz[4];
    if (threadIdx.x < 4) nz[threadIdx.x] = 0;
    __syncthreads();
    int c0 = 0, c1 = 0;
    for (int i = threadIdx.x * 4; i < (1 << 20); i += blockDim.x * 4) {
        uchar4 v = *(const uchar4*)(raw + i);
        c0 += (v.x != 0);
        c1 += (v.y != 0);
    }
    atomicAdd(&nz[0], c0);
    atomicAdd(&nz[1], c1);
    __syncthreads();
    if (threadIdx.x == 0) {
        int mode;
        if (nz[1] > 0)      mode = 0;
        else if (nz[0] > 0) mode = 1;
        else                mode = 2;
        g_mode = mode;
    }
}
__global__ void normalize_mask_kernel(const void* __restrict__ raw,
                                      unsigned char* __restrict__ dst) {
    size_t i = (size_t)blockIdx.x * blockDim.x + threadIdx.x;
    if (i >= NMASK) return;
    int mode = g_mode;
    unsigned char v;
    if (mode == 0)      v = ((const unsigned char*)raw)[i] != 0;
    else if (mode == 1) v = ((const int*)raw)[i] != 0;
    else                v = ((const float*)raw)[i] != 0.0f;
    dst[i] = v;
}

// ---------------------------------------------------------------------------
// coef[b,q] = SCALE / max(1, rowsum(mask))
// ---------------------------------------------------------------------------
__global__ void coef_kernel(const unsigned char* __restrict__ mask,
                            float* __restrict__ coef) {
    int row = blockIdx.x;
    int tid = threadIdx.x;
    const uchar4 v = ((const uchar4*)(mask + (size_t)row * SS))[tid];
    int s = (int)v.x + (int)v.y + (int)v.z + (int)v.w;
#pragma unroll
    for (int o = 16; o; o >>= 1) s += __shfl_xor_sync(0xffffffffu, s, o);
    __shared__ int red[8];
    if ((tid & 31) == 0) red[tid >> 5] = s;
    __syncthreads();
    if (tid < 8) {
        int t = red[tid];
#pragma unroll
        for (int o = 4; o; o >>= 1) t += __shfl_xor_sync(0xffu, t, o);
        if (tid == 0) coef[row] = SCALE / (float)(t > 0 ? t : 1);
    }
}

// ---------------------------------------------------------------------------
// split fp32 -> hi/lo bf16 planes (elementwise, 8 elems/thread)
// ---------------------------------------------------------------------------
__global__ void conv_split_planar(const float* __restrict__ src,
                                  __nv_bfloat16* __restrict__ dh,
                                  __nv_bfloat16* __restrict__ dl, int n) {
    int i0 = (blockIdx.x * blockDim.x + threadIdx.x) * 8;
    if (i0 >= n) return;
    ushort hs[8], ls[8];
#pragma unroll
    for (int j = 0; j < 8; j++) {
        float v = src[i0 + j];
        __nv_bfloat16 h = __float2bfloat16_rn(v);
        __nv_bfloat16 l = __float2bfloat16_rn(v - __bfloat162float(h));
        hs[j] = __bfloat16_as_ushort(h);
        ls[j] = __bfloat16_as_ushort(l);
    }
    uint4 hv = make_uint4((uint32_t)hs[0] | ((uint32_t)hs[1] << 16),
                          (uint32_t)hs[2] | ((uint32_t)hs[3] << 16),
                          (uint32_t)hs[4] | ((uint32_t)hs[5] << 16),
                          (uint32_t)hs[6] | ((uint32_t)hs[7] << 16));
    uint4 lv = make_uint4((uint32_t)ls[0] | ((uint32_t)ls[1] << 16),
                          (uint32_t)ls[2] | ((uint32_t)ls[3] << 16),
                          (uint32_t)ls[4] | ((uint32_t)ls[5] << 16),
                          (uint32_t)ls[6] | ((uint32_t)ls[7] << 16));
    *(uint4*)(dh + i0) = hv;
    *(uint4*)(dl + i0) = lv;
}

// ---------------------------------------------------------------------------
// transpose+split: src [b][k][n] fp32 (1024x1024/b) -> dst planes [b][n][k] bf16
// ---------------------------------------------------------------------------
__global__ void conv_transpose_planar(const float* __restrict__ src,
                                      __nv_bfloat16* __restrict__ dh,
                                      __nv_bfloat16* __restrict__ dl) {
    __shared__ float t[32][33];
    const int b = blockIdx.z;
    const int k0 = blockIdx.y * 32, n0 = blockIdx.x * 32;
    const float* s = src + ((size_t)b << 20);
    const int tx = threadIdx.x, ty = threadIdx.y;    // 32 x 8
#pragma unroll
    for (int j = 0; j < 32; j += 8)
        t[ty + j][tx] = s[(size_t)(k0 + ty + j) * 1024 + n0 + tx];
    __syncthreads();
    const int tid = ty * 32 + tx;
    const int nl = tid >> 3;            // 0..31
    const int kg = (tid & 7) * 4;       // 0..28
    ushort hs[4], ls[4];
#pragma unroll
    for (int i = 0; i < 4; i++) {
        float v = t[kg + i][nl];
        __nv_bfloat16 h = __float2bfloat16_rn(v);
        __nv_bfloat16 l = __float2bfloat16_rn(v - __bfloat162float(h));
        hs[i] = __bfloat16_as_ushort(h);
        ls[i] = __bfloat16_as_ushort(l);
    }
    size_t o = ((size_t)b << 20) + (size_t)(n0 + nl) * 1024 + k0 + kg;
    *(uint2*)(dh + o) = make_uint2((uint32_t)hs[0] | ((uint32_t)hs[1] << 16),
                                   (uint32_t)hs[2] | ((uint32_t)hs[3] << 16));
    *(uint2*)(dl + o) = make_uint2((uint32_t)ls[0] | ((uint32_t)ls[1] << 16),
                                   (uint32_t)ls[2] | ((uint32_t)ls[3] << 16));
}

// ---------------------------------------------------------------------------
// WMMA split-bf16 3-term GEMM (legacy HMMA path — works on compute_103):
//   C[b][m][n] = sum_k (Ah+Al)[m][k] * (Bh+Bl)[b][n][k]  (drops Al*Bl, ~2^-16)
// Virtual K' = 3072: phase 0 Ah*Bh, phase 1 Al*Bh, phase 2 Ah*Bl.
// CTA tile 128x128, 8 warps (2x4), each warp 64x32 = 4x2 wmma 16x16x16 frags.
// ---------------------------------------------------------------------------
#define GBK 32
#define GPAD 40   // smem row stride in bf16 elems (80B, mult of 16B)

__global__ void __launch_bounds__(256, 2)
gemm_wmma(const __nv_bfloat16* __restrict__ Ah, const __nv_bfloat16* __restrict__ Al,
          const __nv_bfloat16* __restrict__ Bh, const __nv_bfloat16* __restrict__ Bl,
          float* __restrict__ C, size_t cStride) {
    __shared__ __nv_bfloat16 As[128][GPAD];
    __shared__ __nv_bfloat16 Bs[128][GPAD];

    const int tid = threadIdx.x;
    const int wid = tid >> 5;
    const int wm = wid >> 2;          // 0..1  (64-row slab)
    const int wn = wid & 3;           // 0..3  (32-col slab)
    const int m0 = blockIdx.y * 128;
    const int n0 = blockIdx.x * 128;
    const size_t bOff = (size_t)blockIdx.z << 20;
    float* Cp = C + (size_t)blockIdx.z * cStride;

    wmma::fragment<wmma::accumulator, 16, 16, 16, float> acc[4][2];
#pragma unroll
    for (int i = 0; i < 4; i++)
#pragma unroll
        for (int j = 0; j < 2; j++) wmma::fill_fragment(acc[i][j], 0.0f);

    for (int vk = 0; vk < 3 * 1024; vk += GBK) {
        const int phase = vk >> 10;          // 0,1,2
        const int kk = vk & 1023;
        const __nv_bfloat16* Ap = (phase == 1) ? Al : Ah;
        const __nv_bfloat16* Bp = ((phase == 2) ? Bl : Bh) + bOff;

        __syncthreads();   // previous iteration's fragment loads done
#pragma unroll
        for (int i = 0; i < 2; i++) {
            int idx = tid + i * 256;          // 0..511
            int r = idx >> 2, seg = (idx & 3) * 8;
            *(uint4*)&As[r][seg] = *(const uint4*)(Ap + (size_t)(m0 + r) * 1024 + kk + seg);
            *(uint4*)&Bs[r][seg] = *(const uint4*)(Bp + (size_t)(n0 + r) * 1024 + kk + seg);
        }
        __syncthreads();

#pragma unroll
        for (int ks = 0; ks < GBK; ks += 16) {
            wmma::fragment<wmma::matrix_a, 16, 16, 16, __nv_bfloat16, wmma::row_major> fa[4];
            wmma::fragment<wmma::matrix_b, 16, 16, 16, __nv_bfloat16, wmma::col_major> fb[2];
#pragma unroll
            for (int i = 0; i < 4; i++)
                wmma::load_matrix_sync(fa[i], &As[wm * 64 + i * 16][ks], GPAD);
#pragma unroll
            for (int j = 0; j < 2; j++)
                wmma::load_matrix_sync(fb[j], &Bs[wn * 32 + j * 16][ks], GPAD);
#pragma unroll
            for (int i = 0; i < 4; i++)
#pragma unroll
                for (int j = 0; j < 2; j++)
                    wmma::mma_sync(acc[i][j], fa[i], fb[j], acc[i][j]);
        }
    }

#pragma unroll
    for (int i = 0; i < 4; i++)
#pragma unroll
        for (int j = 0; j < 2; j++)
            wmma::store_matrix_sync(
                Cp + (size_t)(m0 + wm * 64 + i * 16) * 1024 + n0 + wn * 32 + j * 16,
                acc[i][j], 1024, wmma::mem_row_major);
}

// ---------------------------------------------------------------------------
// Fused masked-relu attention (SIMT, proven in R4)
// ---------------------------------------------------------------------------
#define AS_STRIDE 65
#define ATTN_SMEM_FLOATS (3 * CC * 64 + 64 * AS_STRIDE + 64)
#define ATTN_SMEM_BYTES  (ATTN_SMEM_FLOATS * 4 + 64 * 64)

__global__ void __launch_bounds__(256)
attn_kernel(const float* __restrict__ qkv, const unsigned char* __restrict__ mask,
            const float* __restrict__ coef, float* __restrict__ ctx) {
    extern __shared__ float sm[];
    float* Qs = sm;
    float* Ks = Qs + CC * 64;
    float* Vs = Ks + CC * 64;
    float* As = Vs + CC * 64;
    float* coefs = As + 64 * AS_STRIDE;
    unsigned char* msk = (unsigned char*)(coefs + 64);

    const int q0 = blockIdx.x * 64;
    const int h  = blockIdx.y;
    const int b  = blockIdx.z;
    const int tid = threadIdx.x;

    const float* Qg = qkv + ((size_t)b * 3 * UU + (size_t)h * CC) * SS;
    const float* Kg = Qg + (size_t)UU * SS;
    const float* Vg = Qg + (size_t)2 * UU * SS;
    const unsigned char* mg = mask + ((size_t)b * SS + q0) * SS;

#pragma unroll
    for (int t = 0; t < 8; t++) {
        int idx = tid + t * 256;
        int c = idx >> 4, kg = (idx & 15) << 2;
        *(float4*)&Qs[c * 64 + kg] = *(const float4*)&Qg[(size_t)c * SS + q0 + kg];
    }
    if (tid < 64) coefs[tid] = coef[b * SS + q0 + tid];

    const int qA = (tid & 15) * 4;
    const int kA = (tid >> 4) * 4;
    const int cB = (tid >> 4) * 8;

    float acc[4][8];
#pragma unroll
    for (int i = 0; i < 4; i++)
#pragma unroll
        for (int u = 0; u < 8; u++) acc[i][u] = 0.f;

    for (int kt = 0; kt < SS / 64; kt++) {
        const int k0 = kt * 64;
        __syncthreads();
#pragma unroll
        for (int t = 0; t < 8; t++) {
            int idx = tid + t * 256;
            int c = idx >> 4, kg = (idx & 15) << 2;
            *(float4*)&Ks[c * 64 + kg] = *(const float4*)&Kg[(size_t)c * SS + k0 + kg];
            *(float4*)&Vs[c * 64 + kg] = *(const float4*)&Vg[(size_t)c * SS + k0 + kg];
        }
#pragma unroll
        for (int t = 0; t < 4; t++) {
            int idx = tid + t * 256;
            int q = idx >> 4, kg = (idx & 15) << 2;
            *(uchar4*)&msk[q * 64 + kg] = *(const uchar4*)&mg[(size_t)q * SS + k0 + kg];
        }
        __syncthreads();

        float a4[4][4];
#pragma unroll
        for (int i = 0; i < 4; i++)
#pragma unroll
            for (int j = 0; j < 4; j++) a4[i][j] = 0.f;
#pragma unroll 8
        for (int c = 0; c < CC; c++) {
            float4 qv = *(const float4*)&Qs[c * 64 + qA];
            float4 kv = *(const float4*)&Ks[c * 64 + kA];
            float qr[4] = {qv.x, qv.y, qv.z, qv.w};
            float kr[4] = {kv.x, kv.y, kv.z, kv.w};
#pragma unroll
            for (int i = 0; i < 4; i++)
#pragma unroll
                for (int j = 0; j < 4; j++) a4[i][j] += qr[i] * kr[j];
        }
#pragma unroll
        for (int j = 0; j < 4; j++)
#pragma unroll
            for (int i = 0; i < 4; i++) {
                float v = 0.f;
                if (msk[(qA + i) * 64 + kA + j]) {
                    float r = a4[i][j];
                    v = (r > 0.f ? r : 0.f) * coefs[qA + i];
                }
                As[(kA + j) * AS_STRIDE + qA + i] = v;
            }
        __syncthreads();

#pragma unroll 8
        for (int kk = 0; kk < 64; kk++) {
            float a0 = As[kk * AS_STRIDE + qA + 0];
            float a1 = As[kk * AS_STRIDE + qA + 1];
            float a2 = As[kk * AS_STRIDE + qA + 2];
            float a3 = As[kk * AS_STRIDE + qA + 3];
#pragma unroll
            for (int u = 0; u < 8; u++) {
                float vv = Vs[(cB + u) * 64 + kk];
                acc[0][u] += a0 * vv;
                acc[1][u] += a1 * vv;
                acc[2][u] += a2 * vv;
                acc[3][u] += a3 * vv;
            }
        }
    }

#pragma unroll
    for (int u = 0; u < 8; u++) {
        float* crow = &ctx[((size_t)b * UU + (size_t)h * CC + cB + u) * SS + q0 + qA];
        *(float4*)crow = make_float4(acc[0][u], acc[1][u], acc[2][u], acc[3][u]);
    }
}

// ---------------------------------------------------------------------------
// Launch
// ---------------------------------------------------------------------------
extern "C" void kernel_launch(void* const* d_in, const int* in_sizes, int n_in,
                              void* d_out, int out_size) {
    const float* x     = (const float*)d_in[0];
    const void*  maskr = d_in[1];
    const float* w_qkv = (const float*)d_in[2];
    const float* w_out = (const float*)d_in[3];
    float*       out   = (float*)d_out;

    void *p_qkv, *p_ctx, *p_coef, *p_mask;
    void *p_wqh, *p_wql, *p_woh, *p_wol, *p_xth, *p_xtl, *p_cth, *p_ctl;
    cudaGetSymbolAddress(&p_qkv,  g_qkv);
    cudaGetSymbolAddress(&p_ctx,  g_ctx);
    cudaGetSymbolAddress(&p_coef, g_coef);
    cudaGetSymbolAddress(&p_mask, g_mask);
    cudaGetSymbolAddress(&p_wqh,  g_wq_h);
    cudaGetSymbolAddress(&p_wql,  g_wq_l);
    cudaGetSymbolAddress(&p_woh,  g_wo_h);
    cudaGetSymbolAddress(&p_wol,  g_wo_l);
    cudaGetSymbolAddress(&p_xth,  g_xt_h);
    cudaGetSymbolAddress(&p_xtl,  g_xt_l);
    cudaGetSymbolAddress(&p_cth,  g_ct_h);
    cudaGetSymbolAddress(&p_ctl,  g_ct_l);
    float* qkv  = (float*)p_qkv;
    float* ctx  = (float*)p_ctx;
    float* coef = (float*)p_coef;
    unsigned char* mask = (unsigned char*)p_mask;
    __nv_bfloat16* wqh = (__nv_bfloat16*)p_wqh;
    __nv_bfloat16* wql = (__nv_bfloat16*)p_wql;
    __nv_bfloat16* woh = (__nv_bfloat16*)p_woh;
    __nv_bfloat16* wol = (__nv_bfloat16*)p_wol;
    __nv_bfloat16* xth = (__nv_bfloat16*)p_xth;
    __nv_bfloat16* xtl = (__nv_bfloat16*)p_xtl;
    __nv_bfloat16* cth = (__nv_bfloat16*)p_cth;
    __nv_bfloat16* ctl = (__nv_bfloat16*)p_ctl;

    cudaFuncSetAttribute(attn_kernel, cudaFuncAttributeMaxDynamicSharedMemorySize,
                         ATTN_SMEM_BYTES);

    // mask normalize + coefs
    detect_mask_kernel<<<1, 256>>>((const unsigned char*)maskr);
    normalize_mask_kernel<<<(int)(NMASK / 256), 256>>>(maskr, mask);
    coef_kernel<<<BB * SS, 256>>>(mask, coef);

    // operand prep: split weights; transpose+split x
    conv_split_planar<<<3 * UU * UU / 8 / 256, 256>>>(w_qkv, wqh, wql, 3 * UU * UU);
    conv_split_planar<<<UU * UU / 8 / 256, 256>>>(w_out, woh, wol, UU * UU);
    conv_transpose_planar<<<dim3(32, 32, BB), dim3(32, 8)>>>(x, xth, xtl);

    // QKV projection (WMMA tensor cores): qkv[b] = w_qkv @ x[b]
    gemm_wmma<<<dim3(SS / 128, 3 * UU / 128, BB), 256>>>(
        wqh, wql, xth, xtl, qkv, (size_t)3 * UU * SS);

    // fused attention (fp32 SIMT)
    attn_kernel<<<dim3(SS / 64, HH, BB), 256, ATTN_SMEM_BYTES>>>(
        qkv, mask, coef, ctx);

    // transpose+split ctx, then output projection (WMMA tensor cores)
    conv_transpose_planar<<<dim3(32, 32, BB), dim3(32, 8)>>>(ctx, cth, ctl);
    gemm_wmma<<<dim3(SS / 128, UU / 128, BB), 256>>>(
        woh, wol, cth, ctl, out, (size_t)UU * SS);
}

// round 9
// speedup vs baseline: 1.9387x; 1.4673x over previous
#include <cuda_runtime.h>
#include <cuda_bf16.h>
#include <mma.h>
#include <cstdint>

using namespace nvcuda;

#define BB   16
#define UU   1024
#define HH   8
#define CC   128
#define SS   1024
#define SCALE 0.08838834764831843f   // 1/sqrt(128)

#define NMASK ((size_t)BB * SS * SS)

// ---------------------------------------------------------------------------
// Scratch
// ---------------------------------------------------------------------------
__device__ float g_qkv[(size_t)BB * 3 * UU * SS];        // fp32 QKV, 201 MB
__device__ float g_coef[BB * SS];
__device__ unsigned char g_mask[NMASK];
__device__ int g_mode;
__device__ __nv_bfloat16 g_wq_h[(size_t)3 * UU * UU];
__device__ __nv_bfloat16 g_wq_l[(size_t)3 * UU * UU];
__device__ __nv_bfloat16 g_wo_h[(size_t)UU * UU];
__device__ __nv_bfloat16 g_wo_l[(size_t)UU * UU];
__device__ __nv_bfloat16 g_xt_h[(size_t)BB * UU * SS];   // x^T planes
__device__ __nv_bfloat16 g_xt_l[(size_t)BB * UU * SS];
__device__ __nv_bfloat16 g_qkvh[(size_t)BB * 3 * UU * SS]; // qkv hi plane
__device__ __nv_bfloat16 g_qkvl[(size_t)BB * 3 * UU * SS]; // qkv lo plane
__device__ __nv_bfloat16 g_ct_h[(size_t)BB * UU * SS];   // ctx^T planes [b][s][u]
__device__ __nv_bfloat16 g_ct_l[(size_t)BB * UU * SS];

// ---------------------------------------------------------------------------
// cp.async helpers (sm_80+, fine under compute_103)
// ---------------------------------------------------------------------------
__device__ __forceinline__ uint32_t smaddr(const void* p) {
    return (uint32_t)__cvta_generic_to_shared(p);
}
#define CP16(sm, gp) asm volatile("cp.async.cg.shared.global [%0], [%1], 16;" \
                                  :: "r"(sm), "l"(gp))
#define CP_COMMIT()  asm volatile("cp.async.commit_group;")
#define CP_WAIT1()   asm volatile("cp.async.wait_group 1;")
#define CP_WAIT0()   asm volatile("cp.async.wait_group 0;")

// ---------------------------------------------------------------------------
// Mask detect / normalize (vectorized) + coef
// ---------------------------------------------------------------------------
__global__ void detect_mask_kernel(const unsigned char* __restrict__ raw) {
    __shared__ int nz[4];
    if (threadIdx.x < 4) nz[threadIdx.x] = 0;
    __syncthreads();
    int c0 = 0, c1 = 0;
    for (int i = threadIdx.x * 4; i < (1 << 20); i += blockDim.x * 4) {
        uchar4 v = *(const uchar4*)(raw + i);
        c0 += (v.x != 0);
        c1 += (v.y != 0);
    }
    atomicAdd(&nz[0], c0);
    atomicAdd(&nz[1], c1);
    __syncthreads();
    if (threadIdx.x == 0)
        g_mode = (nz[1] > 0) ? 0 : (nz[0] > 0 ? 1 : 2);
}
__global__ void normalize_mask_kernel(const void* __restrict__ raw,
                                      unsigned char* __restrict__ dst) {
    size_t i = ((size_t)blockIdx.x * blockDim.x + threadIdx.x) * 4;
    if (i >= NMASK) return;
    int mode = g_mode;
    uchar4 o;
    if (mode == 0) {
        uchar4 v = *(const uchar4*)((const unsigned char*)raw + i);
        o = make_uchar4(v.x != 0, v.y != 0, v.z != 0, v.w != 0);
    } else if (mode == 1) {
        int4 v = *(const int4*)((const int*)raw + i);
        o = make_uchar4(v.x != 0, v.y != 0, v.z != 0, v.w != 0);
    } else {
        float4 v = *(const float4*)((const float*)raw + i);
        o = make_uchar4(v.x != 0.f, v.y != 0.f, v.z != 0.f, v.w != 0.f);
    }
    *(uchar4*)(dst + i) = o;
}
__global__ void coef_kernel(const unsigned char* __restrict__ mask,
                            float* __restrict__ coef) {
    int row = blockIdx.x;
    int tid = threadIdx.x;
    const uchar4 v = ((const uchar4*)(mask + (size_t)row * SS))[tid];
    int s = (int)v.x + (int)v.y + (int)v.z + (int)v.w;
#pragma unroll
    for (int o = 16; o; o >>= 1) s += __shfl_xor_sync(0xffffffffu, s, o);
    __shared__ int red[8];
    if ((tid & 31) == 0) red[tid >> 5] = s;
    __syncthreads();
    if (tid < 8) {
        int t = red[tid];
#pragma unroll
        for (int o = 4; o; o >>= 1) t += __shfl_xor_sync(0xffu, t, o);
        if (tid == 0) coef[row] = SCALE / (float)(t > 0 ? t : 1);
    }
}

// ---------------------------------------------------------------------------
// split fp32 -> hi/lo bf16 planes
// ---------------------------------------------------------------------------
__global__ void conv_split_planar(const float* __restrict__ src,
                                  __nv_bfloat16* __restrict__ dh,
                                  __nv_bfloat16* __restrict__ dl, int n) {
    int i0 = (blockIdx.x * blockDim.x + threadIdx.x) * 8;
    if (i0 >= n) return;
    ushort hs[8], ls[8];
#pragma unroll
    for (int j = 0; j < 8; j++) {
        float v = src[i0 + j];
        __nv_bfloat16 h = __float2bfloat16_rn(v);
        __nv_bfloat16 l = __float2bfloat16_rn(v - __bfloat162float(h));
        hs[j] = __bfloat16_as_ushort(h);
        ls[j] = __bfloat16_as_ushort(l);
    }
    *(uint4*)(dh + i0) = make_uint4((uint32_t)hs[0] | ((uint32_t)hs[1] << 16),
                                    (uint32_t)hs[2] | ((uint32_t)hs[3] << 16),
                                    (uint32_t)hs[4] | ((uint32_t)hs[5] << 16),
                                    (uint32_t)hs[6] | ((uint32_t)hs[7] << 16));
    *(uint4*)(dl + i0) = make_uint4((uint32_t)ls[0] | ((uint32_t)ls[1] << 16),
                                    (uint32_t)ls[2] | ((uint32_t)ls[3] << 16),
                                    (uint32_t)ls[4] | ((uint32_t)ls[5] << 16),
                                    (uint32_t)ls[6] | ((uint32_t)ls[7] << 16));
}

// ---------------------------------------------------------------------------
// transpose+split: [b][k][n] fp32 -> [b][n][k] bf16 planes
// ---------------------------------------------------------------------------
__global__ void conv_transpose_planar(const float* __restrict__ src,
                                      __nv_bfloat16* __restrict__ dh,
                                      __nv_bfloat16* __restrict__ dl) {
    __shared__ float t[32][33];
    const int b = blockIdx.z;
    const int k0 = blockIdx.y * 32, n0 = blockIdx.x * 32;
    const float* s = src + ((size_t)b << 20);
    const int tx = threadIdx.x, ty = threadIdx.y;
#pragma unroll
    for (int j = 0; j < 32; j += 8)
        t[ty + j][tx] = s[(size_t)(k0 + ty + j) * 1024 + n0 + tx];
    __syncthreads();
    const int tid = ty * 32 + tx;
    const int nl = tid >> 3;
    const int kg = (tid & 7) * 4;
    ushort hs[4], ls[4];
#pragma unroll
    for (int i = 0; i < 4; i++) {
        float v = t[kg + i][nl];
        __nv_bfloat16 h = __float2bfloat16_rn(v);
        __nv_bfloat16 l = __float2bfloat16_rn(v - __bfloat162float(h));
        hs[i] = __bfloat16_as_ushort(h);
        ls[i] = __bfloat16_as_ushort(l);
    }
    size_t o = ((size_t)b << 20) + (size_t)(n0 + nl) * 1024 + k0 + kg;
    *(uint2*)(dh + o) = make_uint2((uint32_t)hs[0] | ((uint32_t)hs[1] << 16),
                                   (uint32_t)hs[2] | ((uint32_t)hs[3] << 16));
    *(uint2*)(dl + o) = make_uint2((uint32_t)ls[0] | ((uint32_t)ls[1] << 16),
                                   (uint32_t)ls[2] | ((uint32_t)ls[3] << 16));
}

// ---------------------------------------------------------------------------
// WMMA split-bf16 3-term GEMM with cp.async 2-stage pipeline.
// C[b] = (Ah+Al) @ (Bh+Bl)^T  (drops Al*Bl). Virtual K = 3072, BK=32.
// ---------------------------------------------------------------------------
#define GBK 32
#define GPAD 40
#define GCHUNKS 96

__global__ void __launch_bounds__(256, 2)
gemm_wmma(const __nv_bfloat16* __restrict__ Ah, const __nv_bfloat16* __restrict__ Al,
          const __nv_bfloat16* __restrict__ Bh, const __nv_bfloat16* __restrict__ Bl,
          float* __restrict__ C, size_t cStride) {
    __shared__ __align__(16) __nv_bfloat16 As[2][128][GPAD];
    __shared__ __align__(16) __nv_bfloat16 Bs[2][128][GPAD];

    const int tid = threadIdx.x;
    const int wid = tid >> 5;
    const int wm = wid >> 2;
    const int wn = wid & 3;
    const int m0 = blockIdx.y * 128;
    const int n0 = blockIdx.x * 128;
    const size_t bOff = (size_t)blockIdx.z << 20;
    float* Cp = C + (size_t)blockIdx.z * cStride;

    wmma::fragment<wmma::accumulator, 16, 16, 16, float> acc[4][2];
#pragma unroll
    for (int i = 0; i < 4; i++)
#pragma unroll
        for (int j = 0; j < 2; j++) wmma::fill_fragment(acc[i][j], 0.0f);

    auto stage = [&](int c, int buf) {
        const int phase = c >> 5;
        const int kk = (c & 31) * GBK;
        const __nv_bfloat16* Ap = (phase == 1) ? Al : Ah;
        const __nv_bfloat16* Bp = ((phase == 2) ? Bl : Bh) + bOff;
#pragma unroll
        for (int i = 0; i < 2; i++) {
            int idx = tid + i * 256;
            int r = idx >> 2, sg = (idx & 3) * 8;
            CP16(smaddr(&As[buf][r][sg]), Ap + (size_t)(m0 + r) * 1024 + kk + sg);
            CP16(smaddr(&Bs[buf][r][sg]), Bp + (size_t)(n0 + r) * 1024 + kk + sg);
        }
    };

    stage(0, 0);
    CP_COMMIT();

    for (int c = 0; c < GCHUNKS; ++c) {
        if (c + 1 < GCHUNKS) {
            stage(c + 1, (c + 1) & 1);
            CP_COMMIT();
            CP_WAIT1();
        } else {
            CP_WAIT0();
        }
        __syncthreads();
        const int buf = c & 1;
#pragma unroll
        for (int ks = 0; ks < 2; ks++) {
            wmma::fragment<wmma::matrix_a, 16, 16, 16, __nv_bfloat16, wmma::row_major> fa[4];
            wmma::fragment<wmma::matrix_b, 16, 16, 16, __nv_bfloat16, wmma::col_major> fb[2];
#pragma unroll
            for (int i = 0; i < 4; i++)
                wmma::load_matrix_sync(fa[i], &As[buf][wm * 64 + i * 16][ks * 16], GPAD);
#pragma unroll
            for (int j = 0; j < 2; j++)
                wmma::load_matrix_sync(fb[j], &Bs[buf][wn * 32 + j * 16][ks * 16], GPAD);
#pragma unroll
            for (int i = 0; i < 4; i++)
#pragma unroll
                for (int j = 0; j < 2; j++)
                    wmma::mma_sync(acc[i][j], fa[i], fb[j], acc[i][j]);
        }
        __syncthreads();
    }

#pragma unroll
    for (int i = 0; i < 4; i++)
#pragma unroll
        for (int j = 0; j < 2; j++)
            wmma::store_matrix_sync(
                Cp + (size_t)(m0 + wm * 64 + i * 16) * 1024 + n0 + wn * 32 + j * 16,
                acc[i][j], 1024, wmma::mem_row_major);
}

// ---------------------------------------------------------------------------
// WMMA attention: per (b,h,q-tile 128):
//   A = Q^T K (3-term split, K-dim = 3*128), normalize (mask/relu/coef),
//   split A to hi/lo, C += A' V^T (3-term), epilogue -> ctx^T planes [b][s][u].
// ---------------------------------------------------------------------------
#define APAD 136                      // bf16 row stride (272B)
#define FPAD 132                      // fp32 row stride (528B)
#define OFF_AH 0
#define OFF_AL (128 * APAD * 2)                    // 34816
#define OFF_B  (OFF_AL + 128 * APAD * 2)           // 69632 (Asm | Vh+Vl)
#define OFF_QS (OFF_B + 2 * 128 * APAD * 2)        // 139264
#define OFF_KS (OFF_QS + 32 * APAD * 2)            // 147968
#define OFF_CF (OFF_KS + 32 * APAD * 2)            // 156672
#define ATTN_SMEM (OFF_CF + 512)                   // 157184

__global__ void __launch_bounds__(256)
attn_wmma(const __nv_bfloat16* __restrict__ qh, const __nv_bfloat16* __restrict__ ql,
          const unsigned char* __restrict__ mask, const float* __restrict__ coef,
          __nv_bfloat16* __restrict__ cth, __nv_bfloat16* __restrict__ ctl) {
    extern __shared__ char sm[];
    __nv_bfloat16* AhS = (__nv_bfloat16*)(sm + OFF_AH);
    __nv_bfloat16* AlS = (__nv_bfloat16*)(sm + OFF_AL);
    float*         Asm = (float*)(sm + OFF_B);
    __nv_bfloat16* VhS = (__nv_bfloat16*)(sm + OFF_B);
    __nv_bfloat16* VlS = (__nv_bfloat16*)(sm + OFF_B + 128 * APAD * 2);
    __nv_bfloat16* Qs  = (__nv_bfloat16*)(sm + OFF_QS);
    __nv_bfloat16* Ks  = (__nv_bfloat16*)(sm + OFF_KS);
    float*         cfs = (float*)(sm + OFF_CF);

    const int q0 = blockIdx.x * 128;
    const int h  = blockIdx.y;
    const int b  = blockIdx.z;
    const int tid = threadIdx.x;
    const int wid = tid >> 5;
    const int wm = wid >> 2;          // 0..1
    const int wn = wid & 3;           // 0..3

    const size_t base = ((size_t)b * 3 * UU + (size_t)h * CC) * SS;
    const __nv_bfloat16* Qh = qh + base;
    const __nv_bfloat16* Ql = ql + base;
    const __nv_bfloat16* Kh = Qh + (size_t)UU * SS;
    const __nv_bfloat16* Kl = Ql + (size_t)UU * SS;
    const __nv_bfloat16* Vh = Qh + (size_t)2 * UU * SS;
    const __nv_bfloat16* Vl = Ql + (size_t)2 * UU * SS;
    const unsigned char* mg = mask + ((size_t)(b * SS + q0)) * SS;

    if (tid < 128) cfs[tid] = coef[b * SS + q0 + tid];

    wmma::fragment<wmma::accumulator, 16, 16, 16, float> accC[4][2];
#pragma unroll
    for (int i = 0; i < 4; i++)
#pragma unroll
        for (int j = 0; j < 2; j++) wmma::fill_fragment(accC[i][j], 0.0f);

    for (int kt = 0; kt < 8; kt++) {
        const int k0 = kt * 128;

        // ---- QK^T (3-term) ----
        wmma::fragment<wmma::accumulator, 16, 16, 16, float> accA[4][2];
#pragma unroll
        for (int i = 0; i < 4; i++)
#pragma unroll
            for (int j = 0; j < 2; j++) wmma::fill_fragment(accA[i][j], 0.0f);

        for (int ph = 0; ph < 3; ph++) {
            const __nv_bfloat16* Qp = (ph == 1) ? Ql : Qh;
            const __nv_bfloat16* Kp = (ph == 2) ? Kl : Kh;
            for (int cc = 0; cc < 4; cc++) {
                __syncthreads();
#pragma unroll
                for (int i = 0; i < 2; i++) {
                    int idx = tid + i * 256;
                    int r = idx >> 4, sg = (idx & 15) * 8;
                    *(uint4*)&Qs[r * APAD + sg] =
                        *(const uint4*)(Qp + (size_t)(cc * 32 + r) * SS + q0 + sg);
                    *(uint4*)&Ks[r * APAD + sg] =
                        *(const uint4*)(Kp + (size_t)(cc * 32 + r) * SS + k0 + sg);
                }
                __syncthreads();
#pragma unroll
                for (int ks = 0; ks < 2; ks++) {
                    wmma::fragment<wmma::matrix_a, 16, 16, 16, __nv_bfloat16, wmma::col_major> fa[4];
                    wmma::fragment<wmma::matrix_b, 16, 16, 16, __nv_bfloat16, wmma::row_major> fb[2];
#pragma unroll
                    for (int i = 0; i < 4; i++)
                        wmma::load_matrix_sync(fa[i], &Qs[ks * 16 * APAD + wm * 64 + i * 16], APAD);
#pragma unroll
                    for (int j = 0; j < 2; j++)
                        wmma::load_matrix_sync(fb[j], &Ks[ks * 16 * APAD + wn * 32 + j * 16], APAD);
#pragma unroll
                    for (int i = 0; i < 4; i++)
#pragma unroll
                        for (int j = 0; j < 2; j++)
                            wmma::mma_sync(accA[i][j], fa[i], fb[j], accA[i][j]);
                }
            }
        }

        // ---- scores -> smem fp32 ----
        __syncthreads();   // prior k-tile's V reads (region B) complete
#pragma unroll
        for (int i = 0; i < 4; i++)
#pragma unroll
            for (int j = 0; j < 2; j++)
                wmma::store_matrix_sync(
                    &Asm[(size_t)(wm * 64 + i * 16) * FPAD + wn * 32 + j * 16],
                    accA[i][j], FPAD, wmma::mem_row_major);
        __syncthreads();

        // ---- normalize + split (each thread: one q-row half) ----
        {
            const int q = tid >> 1;
            const int hf = tid & 1;
            const float cf = cfs[q];
            const unsigned char* mrow = mg + (size_t)q * SS + k0 + hf * 64;
            uint4 mv[4];
#pragma unroll
            for (int i = 0; i < 4; i++) mv[i] = *(const uint4*)(mrow + i * 16);
            unsigned char mb[64];
            *(uint4*)(mb +  0) = mv[0];
            *(uint4*)(mb + 16) = mv[1];
            *(uint4*)(mb + 32) = mv[2];
            *(uint4*)(mb + 48) = mv[3];
            const int cbase = hf * 64;
#pragma unroll 16
            for (int j = 0; j < 64; j++) {
                float v = Asm[(size_t)q * FPAD + cbase + j];
                v = mb[j] ? fmaxf(v, 0.f) * cf : 0.f;
                __nv_bfloat16 hh = __float2bfloat16_rn(v);
                __nv_bfloat16 ll = __float2bfloat16_rn(v - __bfloat162float(hh));
                AhS[q * APAD + cbase + j] = hh;
                AlS[q * APAD + cbase + j] = ll;
            }
        }
        __syncthreads();   // Asm region free -> stage V

        // ---- stage V tiles (region B) ----
#pragma unroll
        for (int it = 0; it < 16; it++) {
            int idx = tid + (it & 7) * 256;   // 0..2047
            int r = idx >> 4, sg = (idx & 15) * 8;
            __nv_bfloat16* dst = (it < 8) ? VhS : VlS;
            const __nv_bfloat16* src = (it < 8) ? Vh : Vl;
            *(uint4*)&dst[r * APAD + sg] = *(const uint4*)(src + (size_t)r * SS + k0 + sg);
        }
        __syncthreads();

        // ---- A' V^T (3-term): C[q][c] += sum_k A'[q,k] V[c,k] ----
        for (int ph = 0; ph < 3; ph++) {
            const __nv_bfloat16* Ap = (ph == 1) ? AlS : AhS;
            const __nv_bfloat16* Vp = (ph == 2) ? VlS : VhS;
#pragma unroll
            for (int kc = 0; kc < 8; kc++) {
                wmma::fragment<wmma::matrix_a, 16, 16, 16, __nv_bfloat16, wmma::row_major> fa[4];
                wmma::fragment<wmma::matrix_b, 16, 16, 16, __nv_bfloat16, wmma::col_major> fb[2];
#pragma unroll
                for (int i = 0; i < 4; i++)
                    wmma::load_matrix_sync(fa[i], &Ap[(wm * 64 + i * 16) * APAD + kc * 16], APAD);
#pragma unroll
                for (int j = 0; j < 2; j++)
                    wmma::load_matrix_sync(fb[j], &Vp[(wn * 32 + j * 16) * APAD + kc * 16], APAD);
#pragma unroll
                for (int i = 0; i < 4; i++)
#pragma unroll
                    for (int j = 0; j < 2; j++)
                        wmma::mma_sync(accC[i][j], fa[i], fb[j], accC[i][j]);
            }
        }
        __syncthreads();
    }

    // ---- epilogue: C[q][c] -> split planes ct[b][q0+q][h*128+c] ----
#pragma unroll
    for (int i = 0; i < 4; i++)
#pragma unroll
        for (int j = 0; j < 2; j++)
            wmma::store_matrix_sync(
                &Asm[(size_t)(wm * 64 + i * 16) * FPAD + wn * 32 + j * 16],
                accC[i][j], FPAD, wmma::mem_row_major);
    __syncthreads();
    {
        const int q = tid >> 1;
        const int hf = tid & 1;
        ushort hs[8], ls[8];
        size_t o = ((size_t)b << 20) + (size_t)(q0 + q) * 1024 + h * CC + hf * 64;
#pragma unroll
        for (int g = 0; g < 8; g++) {
#pragma unroll
            for (int j = 0; j < 8; j++) {
                float v = Asm[(size_t)q * FPAD + hf * 64 + g * 8 + j];
                __nv_bfloat16 hh = __float2bfloat16_rn(v);
                __nv_bfloat16 ll = __float2bfloat16_rn(v - __bfloat162float(hh));
                hs[j] = __bfloat16_as_ushort(hh);
                ls[j] = __bfloat16_as_ushort(ll);
            }
            *(uint4*)(cth + o + g * 8) =
                make_uint4((uint32_t)hs[0] | ((uint32_t)hs[1] << 16),
                           (uint32_t)hs[2] | ((uint32_t)hs[3] << 16),
                           (uint32_t)hs[4] | ((uint32_t)hs[5] << 16),
                           (uint32_t)hs[6] | ((uint32_t)hs[7] << 16));
            *(uint4*)(ctl + o + g * 8) =
                make_uint4((uint32_t)ls[0] | ((uint32_t)ls[1] << 16),
                           (uint32_t)ls[2] | ((uint32_t)ls[3] << 16),
                           (uint32_t)ls[4] | ((uint32_t)ls[5] << 16),
                           (uint32_t)ls[6] | ((uint32_t)ls[7] << 16));
        }
    }
}

// ---------------------------------------------------------------------------
// Launch
// ---------------------------------------------------------------------------
extern "C" void kernel_launch(void* const* d_in, const int* in_sizes, int n_in,
                              void* d_out, int out_size) {
    const float* x     = (const float*)d_in[0];
    const void*  maskr = d_in[1];
    const float* w_qkv = (const float*)d_in[2];
    const float* w_out = (const float*)d_in[3];
    float*       out   = (float*)d_out;

    void *p_qkv, *p_coef, *p_mask;
    void *p_wqh, *p_wql, *p_woh, *p_wol, *p_xth, *p_xtl;
    void *p_qvh, *p_qvl, *p_cth, *p_ctl;
    cudaGetSymbolAddress(&p_qkv,  g_qkv);
    cudaGetSymbolAddress(&p_coef, g_coef);
    cudaGetSymbolAddress(&p_mask, g_mask);
    cudaGetSymbolAddress(&p_wqh,  g_wq_h);
    cudaGetSymbolAddress(&p_wql,  g_wq_l);
    cudaGetSymbolAddress(&p_woh,  g_wo_h);
    cudaGetSymbolAddress(&p_wol,  g_wo_l);
    cudaGetSymbolAddress(&p_xth,  g_xt_h);
    cudaGetSymbolAddress(&p_xtl,  g_xt_l);
    cudaGetSymbolAddress(&p_qvh,  g_qkvh);
    cudaGetSymbolAddress(&p_qvl,  g_qkvl);
    cudaGetSymbolAddress(&p_cth,  g_ct_h);
    cudaGetSymbolAddress(&p_ctl,  g_ct_l);
    float* qkv  = (float*)p_qkv;
    float* coef = (float*)p_coef;
    unsigned char* mask = (unsigned char*)p_mask;
    __nv_bfloat16* wqh = (__nv_bfloat16*)p_wqh;
    __nv_bfloat16* wql = (__nv_bfloat16*)p_wql;
    __nv_bfloat16* woh = (__nv_bfloat16*)p_woh;
    __nv_bfloat16* wol = (__nv_bfloat16*)p_wol;
    __nv_bfloat16* xth = (__nv_bfloat16*)p_xth;
    __nv_bfloat16* xtl = (__nv_bfloat16*)p_xtl;
    __nv_bfloat16* qvh = (__nv_bfloat16*)p_qvh;
    __nv_bfloat16* qvl = (__nv_bfloat16*)p_qvl;
    __nv_bfloat16* cth = (__nv_bfloat16*)p_cth;
    __nv_bfloat16* ctl = (__nv_bfloat16*)p_ctl;

    cudaFuncSetAttribute(attn_wmma, cudaFuncAttributeMaxDynamicSharedMemorySize,
                         ATTN_SMEM);

    // mask + coef
    detect_mask_kernel<<<1, 256>>>((const unsigned char*)maskr);
    normalize_mask_kernel<<<(int)(NMASK / 4 / 256), 256>>>(maskr, mask);
    coef_kernel<<<BB * SS, 256>>>(mask, coef);

    // operand prep
    conv_split_planar<<<3 * UU * UU / 8 / 256, 256>>>(w_qkv, wqh, wql, 3 * UU * UU);
    conv_split_planar<<<UU * UU / 8 / 256, 256>>>(w_out, woh, wol, UU * UU);
    conv_transpose_planar<<<dim3(32, 32, BB), dim3(32, 8)>>>(x, xth, xtl);

    // QKV projection
    gemm_wmma<<<dim3(SS / 128, 3 * UU / 128, BB), 256>>>(
        wqh, wql, xth, xtl, qkv, (size_t)3 * UU * SS);

    // split qkv -> bf16 planes
    conv_split_planar<<<(int)((size_t)BB * 3 * UU * SS / 8 / 256), 256>>>(
        qkv, qvh, qvl, (int)((size_t)BB * 3 * UU * SS));

    // WMMA attention -> ctx^T planes
    attn_wmma<<<dim3(SS / 128, HH, BB), 256, ATTN_SMEM>>>(
        qvh, qvl, mask, coef, cth, ctl);

    // output projection
    gemm_wmma<<<dim3(SS / 128, UU / 128, BB), 256>>>(
        woh, wol, cth, ctl, out, (size_t)UU * SS);
}